// round 8
// baseline (speedup 1.0000x reference)
#include <cuda_runtime.h>
#include <cuda_fp16.h>
#include <math.h>
#include <stdint.h>

// ---------------------------------------------------------------------------
// Problem constants
// ---------------------------------------------------------------------------
#define T_TOK 4096
#define D_DIM 1024
#define F_DIM 4096
#define E_NUM 8
#define K_TOP 2

#define BM 128
#define BN 256
#define BK 32
#define NSTAGE 5

#define CAPR (T_TOK * K_TOP + E_NUM * BM)   // 9216
#define ROWTILES (CAPR / BM)                // 72

// SMEM stage layout (bytes, within one stage)
#define A_ROWB 80                            // 32 fp16 = 64B + 16B pad
#define B_ROWB 512                           // 256 fp16
#define SM_A    0
#define SM_B    (BM * A_ROWB)                // 10240
#define STAGEB  (SM_B + BK * B_ROWB)         // 26624
#define SM_TOTAL (STAGEB * NSTAGE)           // 133120

// ---------------------------------------------------------------------------
// PTX helpers (sm_103-portable: cp.async + ldmatrix + mma.sync HMMA)
// ---------------------------------------------------------------------------
static __device__ __forceinline__ uint32_t smem_u32(const void* p) {
    uint32_t a;
    asm("{ .reg .u64 t; cvta.to.shared.u64 t, %1; cvt.u32.u64 %0, t; }" : "=r"(a) : "l"(p));
    return a;
}

#define CP16(dst, src) \
    asm volatile("cp.async.cg.shared.global [%0], [%1], 16;" :: "r"(dst), "l"(src))
#define CP_COMMIT() asm volatile("cp.async.commit_group;")
#define CP_WAIT3()  asm volatile("cp.async.wait_group 3;")

#define LDSMX4(R, addr) \
    asm volatile("ldmatrix.sync.aligned.m8n8.x4.shared.b16 {%0,%1,%2,%3}, [%4];" \
        : "=r"((R)[0]), "=r"((R)[1]), "=r"((R)[2]), "=r"((R)[3]) : "r"(addr))
#define LDSMX4T(R, addr) \
    asm volatile("ldmatrix.sync.aligned.m8n8.x4.trans.shared.b16 {%0,%1,%2,%3}, [%4];" \
        : "=r"((R)[0]), "=r"((R)[1]), "=r"((R)[2]), "=r"((R)[3]) : "r"(addr))

#define MMA16816(C, A, B) \
    asm volatile("mma.sync.aligned.m16n8k16.row.col.f32.f16.f16.f32 " \
        "{%0,%1,%2,%3}, {%4,%5,%6,%7}, {%8,%9}, {%0,%1,%2,%3};" \
        : "+f"((C)[0]), "+f"((C)[1]), "+f"((C)[2]), "+f"((C)[3]) \
        : "r"((A)[0]), "r"((A)[1]), "r"((A)[2]), "r"((A)[3]), "r"((B)[0]), "r"((B)[1]))

static __device__ __forceinline__ uint32_t pack_h2(__half a, __half b) {
    return ((uint32_t)__half_as_ushort(b) << 16) | (uint32_t)__half_as_ushort(a);
}

// ---------------------------------------------------------------------------
// Scratch (static device globals)
// ---------------------------------------------------------------------------
__device__ __align__(16) __half g_xf[(size_t)T_TOK * D_DIM];
__device__ __align__(16) __half g_w1f[(size_t)E_NUM * D_DIM * F_DIM];
__device__ __align__(16) __half g_w2f[(size_t)E_NUM * F_DIM * D_DIM];
__device__ __align__(16) __half g_Hf[(size_t)CAPR * F_DIM];
__device__ __align__(16) float g_Y[(size_t)CAPR * D_DIM];
__device__ int   g_rowtok[CAPR];
__device__ int   g_rowpos[T_TOK * K_TOP];
__device__ float g_tokw[T_TOK * K_TOP];
__device__ int   g_toke[T_TOK * K_TOP];
__device__ int   g_cnt[E_NUM];
__device__ int   g_cursor[E_NUM];
__device__ int   g_poff[E_NUM + 1];
__device__ int   g_npad;

// ---------------------------------------------------------------------------
// Routing kernels
// ---------------------------------------------------------------------------
__global__ void reset_kernel() {
    if (threadIdx.x < E_NUM) g_cnt[threadIdx.x] = 0;
}

__global__ void router_kernel(const float* __restrict__ x,
                              const float* __restrict__ rw,
                              const float* __restrict__ rb) {
    int warp = (blockIdx.x * blockDim.x + threadIdx.x) >> 5;
    int lane = threadIdx.x & 31;
    if (warp >= T_TOK) return;
    const float* xr = x + (size_t)warp * D_DIM;
    float acc[E_NUM];
#pragma unroll
    for (int e = 0; e < E_NUM; e++) acc[e] = 0.0f;
    for (int d = lane; d < D_DIM; d += 32) {
        float xv = xr[d];
        const float* w = rw + (size_t)d * E_NUM;
#pragma unroll
        for (int e = 0; e < E_NUM; e++) acc[e] += xv * w[e];
    }
#pragma unroll
    for (int off = 16; off; off >>= 1)
#pragma unroll
        for (int e = 0; e < E_NUM; e++)
            acc[e] += __shfl_down_sync(0xFFFFFFFFu, acc[e], off);
    if (lane == 0) {
        float l[E_NUM];
#pragma unroll
        for (int e = 0; e < E_NUM; e++) l[e] = acc[e] + rb[e];
        int i0 = 0;
#pragma unroll
        for (int e = 1; e < E_NUM; e++) if (l[e] > l[i0]) i0 = e;
        int i1 = -1;
#pragma unroll
        for (int e = 0; e < E_NUM; e++) {
            if (e == i0) continue;
            if (i1 < 0 || l[e] > l[i1]) i1 = e;
        }
        float w0 = 1.0f / (1.0f + expf(l[i1] - l[i0]));
        g_toke[warp * 2 + 0] = i0;
        g_toke[warp * 2 + 1] = i1;
        g_tokw[warp * 2 + 0] = w0;
        g_tokw[warp * 2 + 1] = 1.0f - w0;
        atomicAdd(&g_cnt[i0], 1);
        atomicAdd(&g_cnt[i1], 1);
    }
}

__global__ void setup_kernel() {
    if (threadIdx.x == 0) {
        int off = 0;
        for (int e = 0; e < E_NUM; e++) {
            g_poff[e] = off;
            g_cursor[e] = off;
            off += ((g_cnt[e] + BM - 1) / BM) * BM;
        }
        g_poff[E_NUM] = off;
        g_npad = off;
    }
    __syncthreads();
    for (int i = threadIdx.x; i < CAPR; i += blockDim.x) g_rowtok[i] = 0;
}

__global__ void scatter_kernel() {
    int i = blockIdx.x * blockDim.x + threadIdx.x;
    if (i >= T_TOK * K_TOP) return;
    int e = g_toke[i];
    int p = atomicAdd(&g_cursor[e], 1);
    g_rowtok[p] = i >> 1;
    g_rowpos[i] = p;
}

// ---------------------------------------------------------------------------
// fp32 -> fp16 conversion
// ---------------------------------------------------------------------------
__global__ void convh_kernel(const float4* __restrict__ in, __half* __restrict__ out, int n4) {
    int i = blockIdx.x * blockDim.x + threadIdx.x;
    if (i >= n4) return;
    float4 v = in[i];
    uint32_t w0 = pack_h2(__float2half_rn(v.x), __float2half_rn(v.y));
    uint32_t w1 = pack_h2(__float2half_rn(v.z), __float2half_rn(v.w));
    ((uint2*)out)[i] = make_uint2(w0, w1);
}

// ---------------------------------------------------------------------------
// fp16 HMMA GEMM, BM=128 BN=256 BK=32, 5-stage cp.async pipeline,
// warp tile 64x64 (8 warps, 2x4). GEMM1 variant also hosts w2-conversion
// CTAs at blockIdx.y == ROWTILES (runs in GEMM1's tail wave).
// ---------------------------------------------------------------------------
template<bool GATHER, bool GELU, int KTOT, int NTOT>
__global__ void __launch_bounds__(256, 1)
moe_gemm(const float* __restrict__ bias,
         const float4* __restrict__ cvt_src, __half* __restrict__ cvt_dst, int cvt_n4) {
    // ---- fused conversion CTAs (GEMM1 only) ----
    if (GATHER && blockIdx.y == ROWTILES) {
        int stride = gridDim.x * blockDim.x;
        for (int i = blockIdx.x * blockDim.x + threadIdx.x; i < cvt_n4; i += stride) {
            float4 v = cvt_src[i];
            uint32_t w0 = pack_h2(__float2half_rn(v.x), __float2half_rn(v.y));
            uint32_t w1 = pack_h2(__float2half_rn(v.z), __float2half_rn(v.w));
            ((uint2*)cvt_dst)[i] = make_uint2(w0, w1);
        }
        return;
    }

    int row0 = blockIdx.y * BM;
    if (row0 >= g_npad) return;
    int e = 0;
    while (row0 >= g_poff[e + 1]) e++;
    int n0 = blockIdx.x * BN;

    extern __shared__ char smem[];
    uint32_t su = smem_u32(smem);

    int tid = threadIdx.x;
    int lane = tid & 31;
    int wid = tid >> 5;
    int warp_m = wid & 1;      // 0..1 -> 64 rows each
    int warp_n = wid >> 1;     // 0..3 -> 64 cols each

    // ---- per-thread cp.async source rows
    const __half* a_g;
    {
        int r = tid >> 1;
        if (GATHER) {
            int tok = g_rowtok[row0 + r];
            a_g = g_xf + (size_t)tok * KTOT;
        } else {
            a_g = g_Hf + (size_t)(row0 + r) * KTOT;
        }
    }
    const __half* b_g = (GATHER ? g_w1f : g_w2f) + (size_t)e * KTOT * NTOT;

    // per-thread cp.async dest offsets
    // A: 128 rows x 64B; 2 threads/row, 32B (2 x CP16) each
    int ar = tid >> 1;
    int ac = (tid & 1) * 2;
    uint32_t a_dst = su + ar * A_ROWB + ac * 16;
    // B: 32 rows x 512B; 8 threads/row, 64B (4 x CP16) each
    int bkr = tid >> 3;                            // 0..31
    int bc = (tid & 7) * 4;                        // 16B-chunk base 0..28
    uint32_t b_dst[4];
#pragma unroll
    for (int q = 0; q < 4; q++)
        b_dst[q] = su + SM_B + bkr * B_ROWB + ((((bc + q) * 16)) ^ ((bkr & 7) << 4));

    float acc[4][8][4];
#pragma unroll
    for (int mt = 0; mt < 4; mt++)
#pragma unroll
        for (int nt = 0; nt < 8; nt++)
#pragma unroll
            for (int q = 0; q < 4; q++) acc[mt][nt][q] = 0.0f;

    // ldmatrix per-thread invariant offsets
    uint32_t a_lds = (uint32_t)((warp_m * 64 + (lane & 15)) * A_ROWB + ((lane >> 4) * 8) * 2);
    int krow_base = (lane & 7) + ((lane >> 3) & 1) * 8;
    int nb_base = (warp_n * 64 + ((lane >> 4) & 1) * 8) * 2;   // bytes within 512B row

    const int NK = KTOT / BK;

#define ISSUE_COPY(kc, sb_off)                                                      \
    do {                                                                            \
        int k0_ = (kc) * BK;                                                        \
        const __half* pa_ = a_g + k0_ + ac * 8;                                     \
        CP16((sb_off) + a_dst,      pa_);                                           \
        CP16((sb_off) + a_dst + 16, pa_ + 8);                                       \
        const __half* pb_ = b_g + (size_t)(k0_ + bkr) * NTOT + n0 + bc * 8;         \
        CP16((sb_off) + b_dst[0], pb_);                                             \
        CP16((sb_off) + b_dst[1], pb_ + 8);                                         \
        CP16((sb_off) + b_dst[2], pb_ + 16);                                        \
        CP16((sb_off) + b_dst[3], pb_ + 24);                                        \
    } while (0)

    // prologue: stages 0..3
    ISSUE_COPY(0, 0);
    CP_COMMIT();
    ISSUE_COPY(1, STAGEB);
    CP_COMMIT();
    ISSUE_COPY(2, 2 * STAGEB);
    CP_COMMIT();
    ISSUE_COPY(3, 3 * STAGEB);
    CP_COMMIT();

    int stage = 0;       // buffer index of k-chunk kc
    int stage_w = 4;     // buffer index to write next
    for (int kc = 0; kc < NK; kc++) {
        CP_WAIT3();          // stage for kc complete (<=3 groups pending)
        __syncthreads();     // all reads of buffer (kc-1)%5 done -> safe to fill
        if (kc + 4 < NK) ISSUE_COPY(kc + 4, (uint32_t)stage_w * STAGEB);
        CP_COMMIT();

        uint32_t sb = su + (uint32_t)stage * STAGEB;
#pragma unroll
        for (int ks = 0; ks < 2; ks++) {
            uint32_t a_r[4][4], b_r[8][2];
#pragma unroll
            for (int mt = 0; mt < 4; mt++) {
                uint32_t ad = sb + a_lds + (uint32_t)(mt * 16 * A_ROWB + ks * 32);
                LDSMX4(a_r[mt], ad);
            }
#pragma unroll
            for (int pt = 0; pt < 4; pt++) {
                int krow = ks * 16 + krow_base;
                int nb = nb_base + pt * 32;
                uint32_t bd = sb + SM_B + krow * B_ROWB + (nb ^ ((krow & 7) << 4));
                uint32_t r[4];
                LDSMX4T(r, bd);
                b_r[2 * pt][0] = r[0]; b_r[2 * pt][1] = r[1];
                b_r[2 * pt + 1][0] = r[2]; b_r[2 * pt + 1][1] = r[3];
            }
#pragma unroll
            for (int mt = 0; mt < 4; mt++)
#pragma unroll
                for (int nt = 0; nt < 8; nt++)
                    MMA16816(acc[mt][nt], a_r[mt], b_r[nt]);
        }
        stage = (stage == NSTAGE - 1) ? 0 : stage + 1;
        stage_w = (stage_w == NSTAGE - 1) ? 0 : stage_w + 1;
    }
#undef ISSUE_COPY

    // ---- epilogue
    int tr = lane >> 2;
    int tc = (lane & 3) * 2;
    const float* be = bias + (size_t)e * NTOT;
#pragma unroll
    for (int nt = 0; nt < 8; nt++) {
        int col = n0 + warp_n * 64 + nt * 8 + tc;
        float bv0 = __ldg(be + col);
        float bv1 = __ldg(be + col + 1);
#pragma unroll
        for (int mt = 0; mt < 4; mt++) {
            int rowa = row0 + warp_m * 64 + mt * 16 + tr;
#pragma unroll
            for (int half = 0; half < 2; half++) {
                int row = rowa + half * 8;
                float v0 = acc[mt][nt][2 * half + 0] + bv0;
                float v1 = acc[mt][nt][2 * half + 1] + bv1;
                if (GELU) {
                    v0 = 0.5f * v0 * (1.0f + erff(v0 * 0.70710678118654752f));
                    v1 = 0.5f * v1 * (1.0f + erff(v1 * 0.70710678118654752f));
                    *(uint32_t*)(g_Hf + (size_t)row * F_DIM + col) =
                        pack_h2(__float2half_rn(v0), __float2half_rn(v1));
                } else {
                    float2 o = make_float2(v0, v1);
                    *(float2*)(g_Y + (size_t)row * D_DIM + col) = o;
                }
            }
        }
    }
}

// ---------------------------------------------------------------------------
// Combine
// ---------------------------------------------------------------------------
__global__ void combine_kernel(float* __restrict__ out) {
    int i = blockIdx.x * blockDim.x + threadIdx.x;
    if (i >= T_TOK * (D_DIM / 4)) return;
    int t = i >> 8;
    int c = (i & 255) << 2;
    int p0 = g_rowpos[t * 2 + 0];
    int p1 = g_rowpos[t * 2 + 1];
    float w0 = g_tokw[t * 2 + 0];
    float w1 = g_tokw[t * 2 + 1];
    float4 y0 = *(const float4*)&g_Y[(size_t)p0 * D_DIM + c];
    float4 y1 = *(const float4*)&g_Y[(size_t)p1 * D_DIM + c];
    float4 o;
    o.x = w0 * y0.x + w1 * y1.x;
    o.y = w0 * y0.y + w1 * y1.y;
    o.z = w0 * y0.z + w1 * y1.z;
    o.w = w0 * y0.w + w1 * y1.w;
    *(float4*)&((float*)out)[(size_t)t * D_DIM + c] = o;
}

// ---------------------------------------------------------------------------
// Launch
// ---------------------------------------------------------------------------
extern "C" void kernel_launch(void* const* d_in, const int* in_sizes, int n_in,
                              void* d_out, int out_size) {
    const float* x  = (const float*)d_in[0];
    const float* rw = (const float*)d_in[1];
    const float* rb = (const float*)d_in[2];
    const float* w1 = (const float*)d_in[3];
    const float* b1 = (const float*)d_in[4];
    const float* w2 = (const float*)d_in[5];
    const float* b2 = (const float*)d_in[6];
    float* out = (float*)d_out;

    static bool attr_done = false;
    if (!attr_done) {
        cudaFuncSetAttribute(moe_gemm<true, true, D_DIM, F_DIM>,
                             cudaFuncAttributeMaxDynamicSharedMemorySize, SM_TOTAL);
        cudaFuncSetAttribute(moe_gemm<false, false, F_DIM, D_DIM>,
                             cudaFuncAttributeMaxDynamicSharedMemorySize, SM_TOTAL);
        attr_done = true;
    }

    __half *xf, *w1f, *w2f;
    cudaGetSymbolAddress((void**)&xf, g_xf);
    cudaGetSymbolAddress((void**)&w1f, g_w1f);
    cudaGetSymbolAddress((void**)&w2f, g_w2f);

    reset_kernel<<<1, 32>>>();
    router_kernel<<<(T_TOK * 32 + 255) / 256, 256>>>(x, rw, rb);
    setup_kernel<<<1, 256>>>();
    scatter_kernel<<<(T_TOK * K_TOP + 255) / 256, 256>>>();

    // conversions needed BEFORE GEMM1: x and w1 (w2 is converted inside GEMM1)
    {
        int nx4 = T_TOK * D_DIM / 4;
        convh_kernel<<<(nx4 + 255) / 256, 256>>>((const float4*)x, xf, nx4);
        int n4 = E_NUM * D_DIM * F_DIM / 4;
        convh_kernel<<<(n4 + 255) / 256, 256>>>((const float4*)w1, w1f, n4);
    }

    // GEMM1 grid: y in [0,ROWTILES) = GEMM tiles; y == ROWTILES = w2 conversion
    int w2n4 = E_NUM * F_DIM * D_DIM / 4;
    moe_gemm<true, true, D_DIM, F_DIM>
        <<<dim3(F_DIM / BN, ROWTILES + 1), 256, SM_TOTAL>>>(
            b1, (const float4*)w2, w2f, w2n4);
    moe_gemm<false, false, F_DIM, D_DIM>
        <<<dim3(D_DIM / BN, ROWTILES), 256, SM_TOTAL>>>(b2, nullptr, nullptr, 0);
    combine_kernel<<<(T_TOK * (D_DIM / 4) + 255) / 256, 256>>>(out);
}

// round 9
// speedup vs baseline: 1.6215x; 1.6215x over previous
#include <cuda_runtime.h>
#include <cuda_fp16.h>
#include <math.h>
#include <stdint.h>

// ---------------------------------------------------------------------------
// Problem constants
// ---------------------------------------------------------------------------
#define T_TOK 4096
#define D_DIM 1024
#define F_DIM 4096
#define E_NUM 8
#define K_TOP 2

#define BM 128
#define BN 128
#define BK 32
#define NSTAGE 5

#define CAPR (T_TOK * K_TOP + E_NUM * BM)   // 9216
#define ROWTILES (CAPR / BM)                // 72

// SMEM stage layout (bytes, within one stage)
#define A_ROWB 80                            // 32 fp16 = 64B + 16B pad
#define SM_A    0
#define SM_B    (BM * A_ROWB)                // 10240
#define STAGEB  (SM_B + BK * 256)            // 18432
#define SM_TOTAL (STAGEB * NSTAGE)           // 92160  (x2 CTAs = 180KB < 228KB)

// ---------------------------------------------------------------------------
// PTX helpers (sm_103-portable: cp.async + ldmatrix + mma.sync HMMA)
// ---------------------------------------------------------------------------
static __device__ __forceinline__ uint32_t smem_u32(const void* p) {
    uint32_t a;
    asm("{ .reg .u64 t; cvta.to.shared.u64 t, %1; cvt.u32.u64 %0, t; }" : "=r"(a) : "l"(p));
    return a;
}

#define CP16(dst, src) \
    asm volatile("cp.async.cg.shared.global [%0], [%1], 16;" :: "r"(dst), "l"(src))
#define CP_COMMIT() asm volatile("cp.async.commit_group;")
#define CP_WAIT3()  asm volatile("cp.async.wait_group 3;")

#define LDSMX4(R, addr) \
    asm volatile("ldmatrix.sync.aligned.m8n8.x4.shared.b16 {%0,%1,%2,%3}, [%4];" \
        : "=r"((R)[0]), "=r"((R)[1]), "=r"((R)[2]), "=r"((R)[3]) : "r"(addr))
#define LDSMX4T(R, addr) \
    asm volatile("ldmatrix.sync.aligned.m8n8.x4.trans.shared.b16 {%0,%1,%2,%3}, [%4];" \
        : "=r"((R)[0]), "=r"((R)[1]), "=r"((R)[2]), "=r"((R)[3]) : "r"(addr))

#define MMA16816(C, A, B) \
    asm volatile("mma.sync.aligned.m16n8k16.row.col.f32.f16.f16.f32 " \
        "{%0,%1,%2,%3}, {%4,%5,%6,%7}, {%8,%9}, {%0,%1,%2,%3};" \
        : "+f"((C)[0]), "+f"((C)[1]), "+f"((C)[2]), "+f"((C)[3]) \
        : "r"((A)[0]), "r"((A)[1]), "r"((A)[2]), "r"((A)[3]), "r"((B)[0]), "r"((B)[1]))

static __device__ __forceinline__ uint32_t pack_h2(__half a, __half b) {
    return ((uint32_t)__half_as_ushort(b) << 16) | (uint32_t)__half_as_ushort(a);
}

// ---------------------------------------------------------------------------
// Scratch (static device globals)
// ---------------------------------------------------------------------------
__device__ __align__(16) __half g_xf[(size_t)T_TOK * D_DIM];
__device__ __align__(16) __half g_w1f[(size_t)E_NUM * D_DIM * F_DIM];
__device__ __align__(16) __half g_w2f[(size_t)E_NUM * F_DIM * D_DIM];
__device__ __align__(16) __half g_Hf[(size_t)CAPR * F_DIM];
__device__ __align__(16) float g_Y[(size_t)CAPR * D_DIM];
__device__ int   g_rowtok[CAPR];
__device__ int   g_rowpos[T_TOK * K_TOP];
__device__ float g_tokw[T_TOK * K_TOP];
__device__ int   g_toke[T_TOK * K_TOP];
__device__ int   g_cnt[E_NUM];
__device__ int   g_cursor[E_NUM];
__device__ int   g_poff[E_NUM + 1];
__device__ int   g_npad;

// ---------------------------------------------------------------------------
// Routing kernels
// ---------------------------------------------------------------------------
__global__ void reset_kernel() {
    if (threadIdx.x < E_NUM) g_cnt[threadIdx.x] = 0;
}

__global__ void router_kernel(const float* __restrict__ x,
                              const float* __restrict__ rw,
                              const float* __restrict__ rb) {
    int warp = (blockIdx.x * blockDim.x + threadIdx.x) >> 5;
    int lane = threadIdx.x & 31;
    if (warp >= T_TOK) return;
    const float* xr = x + (size_t)warp * D_DIM;
    float acc[E_NUM];
#pragma unroll
    for (int e = 0; e < E_NUM; e++) acc[e] = 0.0f;
    for (int d = lane; d < D_DIM; d += 32) {
        float xv = xr[d];
        const float* w = rw + (size_t)d * E_NUM;
#pragma unroll
        for (int e = 0; e < E_NUM; e++) acc[e] += xv * w[e];
    }
#pragma unroll
    for (int off = 16; off; off >>= 1)
#pragma unroll
        for (int e = 0; e < E_NUM; e++)
            acc[e] += __shfl_down_sync(0xFFFFFFFFu, acc[e], off);
    if (lane == 0) {
        float l[E_NUM];
#pragma unroll
        for (int e = 0; e < E_NUM; e++) l[e] = acc[e] + rb[e];
        int i0 = 0;
#pragma unroll
        for (int e = 1; e < E_NUM; e++) if (l[e] > l[i0]) i0 = e;
        int i1 = -1;
#pragma unroll
        for (int e = 0; e < E_NUM; e++) {
            if (e == i0) continue;
            if (i1 < 0 || l[e] > l[i1]) i1 = e;
        }
        float w0 = 1.0f / (1.0f + expf(l[i1] - l[i0]));
        g_toke[warp * 2 + 0] = i0;
        g_toke[warp * 2 + 1] = i1;
        g_tokw[warp * 2 + 0] = w0;
        g_tokw[warp * 2 + 1] = 1.0f - w0;
        atomicAdd(&g_cnt[i0], 1);
        atomicAdd(&g_cnt[i1], 1);
    }
}

__global__ void setup_kernel() {
    if (threadIdx.x == 0) {
        int off = 0;
        for (int e = 0; e < E_NUM; e++) {
            g_poff[e] = off;
            g_cursor[e] = off;
            off += ((g_cnt[e] + BM - 1) / BM) * BM;
        }
        g_poff[E_NUM] = off;
        g_npad = off;
    }
    __syncthreads();
    for (int i = threadIdx.x; i < CAPR; i += blockDim.x) g_rowtok[i] = 0;
}

__global__ void scatter_kernel() {
    int i = blockIdx.x * blockDim.x + threadIdx.x;
    if (i >= T_TOK * K_TOP) return;
    int e = g_toke[i];
    int p = atomicAdd(&g_cursor[e], 1);
    g_rowtok[p] = i >> 1;
    g_rowpos[i] = p;
}

// ---------------------------------------------------------------------------
// fp32 -> fp16 conversion
// ---------------------------------------------------------------------------
__global__ void convh_kernel(const float4* __restrict__ in, __half* __restrict__ out, int n4) {
    int i = blockIdx.x * blockDim.x + threadIdx.x;
    if (i >= n4) return;
    float4 v = in[i];
    uint32_t w0 = pack_h2(__float2half_rn(v.x), __float2half_rn(v.y));
    uint32_t w1 = pack_h2(__float2half_rn(v.z), __float2half_rn(v.w));
    ((uint2*)out)[i] = make_uint2(w0, w1);
}

// ---------------------------------------------------------------------------
// fp16 HMMA GEMM (single product), BK=32, 5-stage cp.async pipeline,
// one barrier per k-chunk, chunk-wide B-fragment preload.
// GEMM1 variant hosts the w2->fp16 conversion in its blockIdx.y==0 slice
// (scheduled FIRST, overlapping GEMM1's compute waves).
// ---------------------------------------------------------------------------
template<bool GATHER, bool GELU, int KTOT, int NTOT>
__global__ void __launch_bounds__(256, 2)
moe_gemm(const float* __restrict__ bias,
         const float4* __restrict__ cvt_src, __half* __restrict__ cvt_dst, int cvt_n4) {
    int by = blockIdx.y;
    if (GATHER) {
        if (by == 0) {
            // fused w2 conversion, runs concurrently with GEMM1 tiles
            int stride = gridDim.x * blockDim.x;
            int base = blockIdx.x * blockDim.x + threadIdx.x;
            for (int i = base; i < cvt_n4; i += 4 * stride) {
#pragma unroll
                for (int u = 0; u < 4; u++) {
                    int j = i + u * stride;
                    if (j < cvt_n4) {
                        float4 v = cvt_src[j];
                        uint32_t w0 = pack_h2(__float2half_rn(v.x), __float2half_rn(v.y));
                        uint32_t w1 = pack_h2(__float2half_rn(v.z), __float2half_rn(v.w));
                        ((uint2*)cvt_dst)[j] = make_uint2(w0, w1);
                    }
                }
            }
            return;
        }
        by -= 1;
    }

    int row0 = by * BM;
    if (row0 >= g_npad) return;
    int e = 0;
    while (row0 >= g_poff[e + 1]) e++;
    int n0 = blockIdx.x * BN;

    extern __shared__ char smem[];
    uint32_t su = smem_u32(smem);

    int tid = threadIdx.x;
    int lane = tid & 31;
    int wid = tid >> 5;
    int warp_m = wid & 1;      // 0..1 -> 64 rows each
    int warp_n = wid >> 1;     // 0..3 -> 32 cols each

    // ---- per-thread cp.async source rows
    const __half* a_g;
    {
        int r = tid >> 1;
        if (GATHER) {
            int tok = g_rowtok[row0 + r];
            a_g = g_xf + (size_t)tok * KTOT;
        } else {
            a_g = g_Hf + (size_t)(row0 + r) * KTOT;
        }
    }
    const __half* b_g = (GATHER ? g_w1f : g_w2f) + (size_t)e * KTOT * NTOT;

    // per-thread cp.async dest offsets
    int ar = tid >> 1;
    int ac = (tid & 1) * 2;                        // A 16B-chunk base (0 or 2)
    uint32_t a_dst = su + ar * A_ROWB + ac * 16;
    int bkr = tid >> 3;                            // B k-row 0..31
    int bc = (tid & 7) * 2;                        // B 16B-chunk base
    uint32_t b_dst0 = su + SM_B + bkr * 256 + ((bc * 16) ^ ((bkr & 7) << 4));
    uint32_t b_dst1 = su + SM_B + bkr * 256 + (((bc + 1) * 16) ^ ((bkr & 7) << 4));

    float acc[4][4][4];
#pragma unroll
    for (int mt = 0; mt < 4; mt++)
#pragma unroll
        for (int nt = 0; nt < 4; nt++)
#pragma unroll
            for (int q = 0; q < 4; q++) acc[mt][nt][q] = 0.0f;

    // ldmatrix per-thread invariant offsets
    uint32_t a_lds = (uint32_t)((warp_m * 64 + (lane & 15)) * A_ROWB + ((lane >> 4) * 8) * 2);
    int krow_base = (lane & 7) + ((lane >> 3) & 1) * 8;
    int nb_base = (warp_n * 32 + ((lane >> 4) & 1) * 8) * 2;

    const int NK = KTOT / BK;

#define ISSUE_COPY(kc, sb_off)                                                      \
    do {                                                                            \
        int k0_ = (kc) * BK;                                                        \
        const __half* pa_ = a_g + k0_ + ac * 8;                                     \
        CP16((sb_off) + a_dst, pa_); CP16((sb_off) + a_dst + 16, pa_ + 8);          \
        const __half* pb_ = b_g + (size_t)(k0_ + bkr) * NTOT + n0 + bc * 8;         \
        CP16((sb_off) + b_dst0, pb_); CP16((sb_off) + b_dst1, pb_ + 8);             \
    } while (0)

    // prologue: stages 0..3
    ISSUE_COPY(0, 0);
    CP_COMMIT();
    ISSUE_COPY(1, STAGEB);
    CP_COMMIT();
    ISSUE_COPY(2, 2 * STAGEB);
    CP_COMMIT();
    ISSUE_COPY(3, 3 * STAGEB);
    CP_COMMIT();

    int stage = 0;       // buffer index of k-chunk kc
    int stage_w = 4;     // buffer index to write next
    for (int kc = 0; kc < NK; kc++) {
        CP_WAIT3();          // stage for kc complete (<=3 groups pending)
        __syncthreads();     // all reads of buffer (kc-1)%5 done -> safe to fill
        if (kc + 4 < NK) ISSUE_COPY(kc + 4, (uint32_t)stage_w * STAGEB);
        CP_COMMIT();

        uint32_t sb = su + (uint32_t)stage * STAGEB;

        // preload ALL B fragments for the chunk (both k-steps)
        uint32_t b_r[2][4][2];
#pragma unroll
        for (int ks = 0; ks < 2; ks++) {
#pragma unroll
            for (int pt = 0; pt < 2; pt++) {
                int krow = ks * 16 + krow_base;
                int nb = nb_base + pt * 32;
                uint32_t bd = sb + SM_B + krow * 256 + (nb ^ ((krow & 7) << 4));
                uint32_t r[4];
                LDSMX4T(r, bd);
                b_r[ks][2 * pt][0] = r[0]; b_r[ks][2 * pt][1] = r[1];
                b_r[ks][2 * pt + 1][0] = r[2]; b_r[ks][2 * pt + 1][1] = r[3];
            }
        }
#pragma unroll
        for (int ks = 0; ks < 2; ks++) {
            uint32_t a_r[4][4];
#pragma unroll
            for (int mt = 0; mt < 4; mt++) {
                uint32_t ad = sb + a_lds + (uint32_t)(mt * 16 * A_ROWB + ks * 32);
                LDSMX4(a_r[mt], ad);
            }
#pragma unroll
            for (int mt = 0; mt < 4; mt++)
#pragma unroll
                for (int nt = 0; nt < 4; nt++)
                    MMA16816(acc[mt][nt], a_r[mt], b_r[ks][nt]);
        }
        stage = (stage == NSTAGE - 1) ? 0 : stage + 1;
        stage_w = (stage_w == NSTAGE - 1) ? 0 : stage_w + 1;
    }
#undef ISSUE_COPY

    // ---- epilogue
    int tr = lane >> 2;
    int tc = (lane & 3) * 2;
    const float* be = bias + (size_t)e * NTOT;
#pragma unroll
    for (int nt = 0; nt < 4; nt++) {
        int col = n0 + warp_n * 32 + nt * 8 + tc;
        float bv0 = __ldg(be + col);
        float bv1 = __ldg(be + col + 1);
#pragma unroll
        for (int mt = 0; mt < 4; mt++) {
            int rowa = row0 + warp_m * 64 + mt * 16 + tr;
#pragma unroll
            for (int half = 0; half < 2; half++) {
                int row = rowa + half * 8;
                float v0 = acc[mt][nt][2 * half + 0] + bv0;
                float v1 = acc[mt][nt][2 * half + 1] + bv1;
                if (GELU) {
                    v0 = 0.5f * v0 * (1.0f + erff(v0 * 0.70710678118654752f));
                    v1 = 0.5f * v1 * (1.0f + erff(v1 * 0.70710678118654752f));
                    *(uint32_t*)(g_Hf + (size_t)row * F_DIM + col) =
                        pack_h2(__float2half_rn(v0), __float2half_rn(v1));
                } else {
                    float2 o = make_float2(v0, v1);
                    *(float2*)(g_Y + (size_t)row * D_DIM + col) = o;
                }
            }
        }
    }
}

// ---------------------------------------------------------------------------
// Combine
// ---------------------------------------------------------------------------
__global__ void combine_kernel(float* __restrict__ out) {
    int i = blockIdx.x * blockDim.x + threadIdx.x;
    if (i >= T_TOK * (D_DIM / 4)) return;
    int t = i >> 8;
    int c = (i & 255) << 2;
    int p0 = g_rowpos[t * 2 + 0];
    int p1 = g_rowpos[t * 2 + 1];
    float w0 = g_tokw[t * 2 + 0];
    float w1 = g_tokw[t * 2 + 1];
    float4 y0 = *(const float4*)&g_Y[(size_t)p0 * D_DIM + c];
    float4 y1 = *(const float4*)&g_Y[(size_t)p1 * D_DIM + c];
    float4 o;
    o.x = w0 * y0.x + w1 * y1.x;
    o.y = w0 * y0.y + w1 * y1.y;
    o.z = w0 * y0.z + w1 * y1.z;
    o.w = w0 * y0.w + w1 * y1.w;
    *(float4*)&((float*)out)[(size_t)t * D_DIM + c] = o;
}

// ---------------------------------------------------------------------------
// Launch
// ---------------------------------------------------------------------------
extern "C" void kernel_launch(void* const* d_in, const int* in_sizes, int n_in,
                              void* d_out, int out_size) {
    const float* x  = (const float*)d_in[0];
    const float* rw = (const float*)d_in[1];
    const float* rb = (const float*)d_in[2];
    const float* w1 = (const float*)d_in[3];
    const float* b1 = (const float*)d_in[4];
    const float* w2 = (const float*)d_in[5];
    const float* b2 = (const float*)d_in[6];
    float* out = (float*)d_out;

    static bool attr_done = false;
    if (!attr_done) {
        cudaFuncSetAttribute(moe_gemm<true, true, D_DIM, F_DIM>,
                             cudaFuncAttributeMaxDynamicSharedMemorySize, SM_TOTAL);
        cudaFuncSetAttribute(moe_gemm<false, false, F_DIM, D_DIM>,
                             cudaFuncAttributeMaxDynamicSharedMemorySize, SM_TOTAL);
        attr_done = true;
    }

    __half *xf, *w1f, *w2f;
    cudaGetSymbolAddress((void**)&xf, g_xf);
    cudaGetSymbolAddress((void**)&w1f, g_w1f);
    cudaGetSymbolAddress((void**)&w2f, g_w2f);

    reset_kernel<<<1, 32>>>();
    router_kernel<<<(T_TOK * 32 + 255) / 256, 256>>>(x, rw, rb);
    setup_kernel<<<1, 256>>>();
    scatter_kernel<<<(T_TOK * K_TOP + 255) / 256, 256>>>();

    // conversions needed BEFORE GEMM1: x and w1 (w2 converts inside GEMM1)
    {
        int nx4 = T_TOK * D_DIM / 4;
        convh_kernel<<<(nx4 + 255) / 256, 256>>>((const float4*)x, xf, nx4);
        int n4 = E_NUM * D_DIM * F_DIM / 4;
        convh_kernel<<<(n4 + 255) / 256, 256>>>((const float4*)w1, w1f, n4);
    }

    // GEMM1 grid: y==0 -> w2 conversion (overlapped); y in [1,ROWTILES] -> tiles
    int w2n4 = E_NUM * F_DIM * D_DIM / 4;
    moe_gemm<true, true, D_DIM, F_DIM>
        <<<dim3(F_DIM / BN, ROWTILES + 1), 256, SM_TOTAL>>>(
            b1, (const float4*)w2, w2f, w2n4);
    moe_gemm<false, false, F_DIM, D_DIM>
        <<<dim3(D_DIM / BN, ROWTILES), 256, SM_TOTAL>>>(b2, nullptr, nullptr, 0);
    combine_kernel<<<(T_TOK * (D_DIM / 4) + 255) / 256, 256>>>(out);
}

// round 10
// speedup vs baseline: 1.6952x; 1.0455x over previous
#include <cuda_runtime.h>
#include <cuda_fp16.h>
#include <math.h>
#include <stdint.h>

// ---------------------------------------------------------------------------
// Problem constants
// ---------------------------------------------------------------------------
#define T_TOK 4096
#define D_DIM 1024
#define F_DIM 4096
#define E_NUM 8
#define K_TOP 2

#define BM 128
#define BN 128
#define BK 32
#define NSTAGE 5

#define CAPR (T_TOK * K_TOP + E_NUM * BM)   // 9216
#define ROWTILES (CAPR / BM)                // 72

// SMEM stage layout (bytes, within one stage)
#define A_ROWB 80                            // 32 fp16 = 64B + 16B pad
#define SM_A    0
#define SM_B    (BM * A_ROWB)                // 10240
#define STAGEB  (SM_B + BK * 256)            // 18432
#define SM_TOTAL (STAGEB * NSTAGE)           // 92160  (x2 CTAs = 180KB < 228KB)

// ---------------------------------------------------------------------------
// PTX helpers (sm_103-portable: cp.async + ldmatrix + mma.sync HMMA)
// ---------------------------------------------------------------------------
static __device__ __forceinline__ uint32_t smem_u32(const void* p) {
    uint32_t a;
    asm("{ .reg .u64 t; cvta.to.shared.u64 t, %1; cvt.u32.u64 %0, t; }" : "=r"(a) : "l"(p));
    return a;
}

#define CP16(dst, src) \
    asm volatile("cp.async.cg.shared.global [%0], [%1], 16;" :: "r"(dst), "l"(src))
#define CP_COMMIT() asm volatile("cp.async.commit_group;")
#define CP_WAIT3()  asm volatile("cp.async.wait_group 3;")

#define LDSMX4(R, addr) \
    asm volatile("ldmatrix.sync.aligned.m8n8.x4.shared.b16 {%0,%1,%2,%3}, [%4];" \
        : "=r"((R)[0]), "=r"((R)[1]), "=r"((R)[2]), "=r"((R)[3]) : "r"(addr))
#define LDSMX4T(R, addr) \
    asm volatile("ldmatrix.sync.aligned.m8n8.x4.trans.shared.b16 {%0,%1,%2,%3}, [%4];" \
        : "=r"((R)[0]), "=r"((R)[1]), "=r"((R)[2]), "=r"((R)[3]) : "r"(addr))

#define MMA16816(C, A, B) \
    asm volatile("mma.sync.aligned.m16n8k16.row.col.f32.f16.f16.f32 " \
        "{%0,%1,%2,%3}, {%4,%5,%6,%7}, {%8,%9}, {%0,%1,%2,%3};" \
        : "+f"((C)[0]), "+f"((C)[1]), "+f"((C)[2]), "+f"((C)[3]) \
        : "r"((A)[0]), "r"((A)[1]), "r"((A)[2]), "r"((A)[3]), "r"((B)[0]), "r"((B)[1]))

#define REDADD2(addr, v0, v1) \
    asm volatile("red.global.add.v2.f32 [%0], {%1, %2};" :: "l"(addr), "f"(v0), "f"(v1) : "memory")

static __device__ __forceinline__ uint32_t pack_h2(__half a, __half b) {
    return ((uint32_t)__half_as_ushort(b) << 16) | (uint32_t)__half_as_ushort(a);
}

// ---------------------------------------------------------------------------
// Scratch (static device globals)
// ---------------------------------------------------------------------------
__device__ __align__(16) __half g_xf[(size_t)T_TOK * D_DIM];
__device__ __align__(16) __half g_w1f[(size_t)E_NUM * D_DIM * F_DIM];
__device__ __align__(16) __half g_w2f[(size_t)E_NUM * F_DIM * D_DIM];
__device__ __align__(16) __half g_Hf[(size_t)CAPR * F_DIM];
__device__ int   g_rowtok[CAPR];
__device__ float g_roww[CAPR];
__device__ float g_tokw[T_TOK * K_TOP];
__device__ int   g_toke[T_TOK * K_TOP];
__device__ int   g_cnt[E_NUM];
__device__ int   g_cursor[E_NUM];
__device__ int   g_poff[E_NUM + 1];
__device__ int   g_npad;

// ---------------------------------------------------------------------------
// K0: reset per-launch state (graph replays!)
// ---------------------------------------------------------------------------
__global__ void reset_kernel() {
    if (threadIdx.x < E_NUM) g_cnt[threadIdx.x] = 0;
}

// ---------------------------------------------------------------------------
// Fused prep kernel (grid.y slices, all concurrent):
//   y==0: router (1 warp/token)
//   y==1: x -> fp16
//   y==2: w1 -> fp16 (grid-stride)
//   y==3: zero out[] (accumulated into by GEMM2 epilogue)
// ---------------------------------------------------------------------------
__global__ void __launch_bounds__(256)
prep_kernel(const float* __restrict__ x,
            const float* __restrict__ rw,
            const float* __restrict__ rb,
            const float4* __restrict__ w1,
            float* __restrict__ out) {
    int slice = blockIdx.y;
    if (slice == 0) {
        // ---- router ----
        int warp = blockIdx.x * 8 + (threadIdx.x >> 5);
        int lane = threadIdx.x & 31;
        if (warp >= T_TOK) return;
        const float* xr = x + (size_t)warp * D_DIM;
        float acc[E_NUM];
#pragma unroll
        for (int e = 0; e < E_NUM; e++) acc[e] = 0.0f;
        for (int d = lane; d < D_DIM; d += 32) {
            float xv = xr[d];
            const float* w = rw + (size_t)d * E_NUM;
#pragma unroll
            for (int e = 0; e < E_NUM; e++) acc[e] += xv * w[e];
        }
#pragma unroll
        for (int off = 16; off; off >>= 1)
#pragma unroll
            for (int e = 0; e < E_NUM; e++)
                acc[e] += __shfl_down_sync(0xFFFFFFFFu, acc[e], off);
        if (lane == 0) {
            float l[E_NUM];
#pragma unroll
            for (int e = 0; e < E_NUM; e++) l[e] = acc[e] + rb[e];
            int i0 = 0;
#pragma unroll
            for (int e = 1; e < E_NUM; e++) if (l[e] > l[i0]) i0 = e;
            int i1 = -1;
#pragma unroll
            for (int e = 0; e < E_NUM; e++) {
                if (e == i0) continue;
                if (i1 < 0 || l[e] > l[i1]) i1 = e;
            }
            float w0 = 1.0f / (1.0f + expf(l[i1] - l[i0]));
            g_toke[warp * 2 + 0] = i0;
            g_toke[warp * 2 + 1] = i1;
            g_tokw[warp * 2 + 0] = w0;
            g_tokw[warp * 2 + 1] = 1.0f - w0;
            atomicAdd(&g_cnt[i0], 1);
            atomicAdd(&g_cnt[i1], 1);
        }
    } else if (slice == 1) {
        // ---- x -> fp16 ----
        const float4* in = (const float4*)x;
        const int n4 = T_TOK * D_DIM / 4;
        int stride = gridDim.x * blockDim.x;
        for (int i = blockIdx.x * blockDim.x + threadIdx.x; i < n4; i += stride) {
            float4 v = in[i];
            uint32_t a = pack_h2(__float2half_rn(v.x), __float2half_rn(v.y));
            uint32_t b = pack_h2(__float2half_rn(v.z), __float2half_rn(v.w));
            ((uint2*)g_xf)[i] = make_uint2(a, b);
        }
    } else if (slice == 2) {
        // ---- w1 -> fp16 ----
        const int n4 = E_NUM * D_DIM * F_DIM / 4;
        int stride = gridDim.x * blockDim.x;
        for (int i = blockIdx.x * blockDim.x + threadIdx.x; i < n4; i += stride) {
            float4 v = w1[i];
            uint32_t a = pack_h2(__float2half_rn(v.x), __float2half_rn(v.y));
            uint32_t b = pack_h2(__float2half_rn(v.z), __float2half_rn(v.w));
            ((uint2*)g_w1f)[i] = make_uint2(a, b);
        }
    } else {
        // ---- zero out[] ----
        float4* o4 = (float4*)out;
        const int n4 = T_TOK * D_DIM / 4;
        int stride = gridDim.x * blockDim.x;
        float4 z = make_float4(0.f, 0.f, 0.f, 0.f);
        for (int i = blockIdx.x * blockDim.x + threadIdx.x; i < n4; i += stride)
            o4[i] = z;
    }
}

__global__ void setup_kernel() {
    if (threadIdx.x == 0) {
        int off = 0;
        for (int e = 0; e < E_NUM; e++) {
            g_poff[e] = off;
            g_cursor[e] = off;
            off += ((g_cnt[e] + BM - 1) / BM) * BM;
        }
        g_poff[E_NUM] = off;
        g_npad = off;
    }
    __syncthreads();
    for (int i = threadIdx.x; i < CAPR; i += blockDim.x) {
        g_rowtok[i] = 0;
        g_roww[i] = 0.0f;     // padding rows contribute nothing
    }
}

__global__ void scatter_kernel() {
    int i = blockIdx.x * blockDim.x + threadIdx.x;
    if (i >= T_TOK * K_TOP) return;
    int e = g_toke[i];
    int p = atomicAdd(&g_cursor[e], 1);
    g_rowtok[p] = i >> 1;
    g_roww[p] = g_tokw[i];
}

// ---------------------------------------------------------------------------
// fp16 HMMA GEMM (single product), BK=32, 5-stage cp.async pipeline,
// one barrier per k-chunk, chunk-wide B-fragment preload.
// GEMM1 (GATHER): hosts w2->fp16 conversion at blockIdx.y==0; epilogue
//                 bias+GELU -> g_Hf.
// GEMM2 (!GATHER): epilogue w*(acc+bias) accumulated into out[] via red.v2.f32.
// ---------------------------------------------------------------------------
template<bool GATHER, int KTOT, int NTOT>
__global__ void __launch_bounds__(256, 2)
moe_gemm(const float* __restrict__ bias, float* __restrict__ out,
         const float4* __restrict__ cvt_src, __half* __restrict__ cvt_dst, int cvt_n4) {
    int by = blockIdx.y;
    if (GATHER) {
        if (by == 0) {
            int stride = gridDim.x * blockDim.x;
            int base = blockIdx.x * blockDim.x + threadIdx.x;
            for (int i = base; i < cvt_n4; i += 4 * stride) {
#pragma unroll
                for (int u = 0; u < 4; u++) {
                    int j = i + u * stride;
                    if (j < cvt_n4) {
                        float4 v = cvt_src[j];
                        uint32_t w0 = pack_h2(__float2half_rn(v.x), __float2half_rn(v.y));
                        uint32_t w1 = pack_h2(__float2half_rn(v.z), __float2half_rn(v.w));
                        ((uint2*)cvt_dst)[j] = make_uint2(w0, w1);
                    }
                }
            }
            return;
        }
        by -= 1;
    }

    int row0 = by * BM;
    if (row0 >= g_npad) return;
    int e = 0;
    while (row0 >= g_poff[e + 1]) e++;
    int n0 = blockIdx.x * BN;

    extern __shared__ char smem[];
    uint32_t su = smem_u32(smem);

    int tid = threadIdx.x;
    int lane = tid & 31;
    int wid = tid >> 5;
    int warp_m = wid & 1;      // 0..1 -> 64 rows each
    int warp_n = wid >> 1;     // 0..3 -> 32 cols each

    const __half* a_g;
    {
        int r = tid >> 1;
        if (GATHER) {
            int tok = g_rowtok[row0 + r];
            a_g = g_xf + (size_t)tok * KTOT;
        } else {
            a_g = g_Hf + (size_t)(row0 + r) * KTOT;
        }
    }
    const __half* b_g = (GATHER ? g_w1f : g_w2f) + (size_t)e * KTOT * NTOT;

    int ar = tid >> 1;
    int ac = (tid & 1) * 2;
    uint32_t a_dst = su + ar * A_ROWB + ac * 16;
    int bkr = tid >> 3;
    int bc = (tid & 7) * 2;
    uint32_t b_dst0 = su + SM_B + bkr * 256 + ((bc * 16) ^ ((bkr & 7) << 4));
    uint32_t b_dst1 = su + SM_B + bkr * 256 + (((bc + 1) * 16) ^ ((bkr & 7) << 4));

    float acc[4][4][4];
#pragma unroll
    for (int mt = 0; mt < 4; mt++)
#pragma unroll
        for (int nt = 0; nt < 4; nt++)
#pragma unroll
            for (int q = 0; q < 4; q++) acc[mt][nt][q] = 0.0f;

    uint32_t a_lds = (uint32_t)((warp_m * 64 + (lane & 15)) * A_ROWB + ((lane >> 4) * 8) * 2);
    int krow_base = (lane & 7) + ((lane >> 3) & 1) * 8;
    int nb_base = (warp_n * 32 + ((lane >> 4) & 1) * 8) * 2;

    const int NK = KTOT / BK;

#define ISSUE_COPY(kc, sb_off)                                                      \
    do {                                                                            \
        int k0_ = (kc) * BK;                                                        \
        const __half* pa_ = a_g + k0_ + ac * 8;                                     \
        CP16((sb_off) + a_dst, pa_); CP16((sb_off) + a_dst + 16, pa_ + 8);          \
        const __half* pb_ = b_g + (size_t)(k0_ + bkr) * NTOT + n0 + bc * 8;         \
        CP16((sb_off) + b_dst0, pb_); CP16((sb_off) + b_dst1, pb_ + 8);             \
    } while (0)

    ISSUE_COPY(0, 0);
    CP_COMMIT();
    ISSUE_COPY(1, STAGEB);
    CP_COMMIT();
    ISSUE_COPY(2, 2 * STAGEB);
    CP_COMMIT();
    ISSUE_COPY(3, 3 * STAGEB);
    CP_COMMIT();

    int stage = 0;
    int stage_w = 4;
    for (int kc = 0; kc < NK; kc++) {
        CP_WAIT3();
        __syncthreads();
        if (kc + 4 < NK) ISSUE_COPY(kc + 4, (uint32_t)stage_w * STAGEB);
        CP_COMMIT();

        uint32_t sb = su + (uint32_t)stage * STAGEB;

        uint32_t b_r[2][4][2];
#pragma unroll
        for (int ks = 0; ks < 2; ks++) {
#pragma unroll
            for (int pt = 0; pt < 2; pt++) {
                int krow = ks * 16 + krow_base;
                int nb = nb_base + pt * 32;
                uint32_t bd = sb + SM_B + krow * 256 + (nb ^ ((krow & 7) << 4));
                uint32_t r[4];
                LDSMX4T(r, bd);
                b_r[ks][2 * pt][0] = r[0]; b_r[ks][2 * pt][1] = r[1];
                b_r[ks][2 * pt + 1][0] = r[2]; b_r[ks][2 * pt + 1][1] = r[3];
            }
        }
#pragma unroll
        for (int ks = 0; ks < 2; ks++) {
            uint32_t a_r[4][4];
#pragma unroll
            for (int mt = 0; mt < 4; mt++) {
                uint32_t ad = sb + a_lds + (uint32_t)(mt * 16 * A_ROWB + ks * 32);
                LDSMX4(a_r[mt], ad);
            }
#pragma unroll
            for (int mt = 0; mt < 4; mt++)
#pragma unroll
                for (int nt = 0; nt < 4; nt++)
                    MMA16816(acc[mt][nt], a_r[mt], b_r[ks][nt]);
        }
        stage = (stage == NSTAGE - 1) ? 0 : stage + 1;
        stage_w = (stage_w == NSTAGE - 1) ? 0 : stage_w + 1;
    }
#undef ISSUE_COPY

    // ---- epilogue
    int tr = lane >> 2;
    int tc = (lane & 3) * 2;
    const float* be = bias + (size_t)e * NTOT;
#pragma unroll
    for (int nt = 0; nt < 4; nt++) {
        int col = n0 + warp_n * 32 + nt * 8 + tc;
        float bv0 = __ldg(be + col);
        float bv1 = __ldg(be + col + 1);
#pragma unroll
        for (int mt = 0; mt < 4; mt++) {
            int rowa = row0 + warp_m * 64 + mt * 16 + tr;
#pragma unroll
            for (int half = 0; half < 2; half++) {
                int row = rowa + half * 8;
                float v0 = acc[mt][nt][2 * half + 0] + bv0;
                float v1 = acc[mt][nt][2 * half + 1] + bv1;
                if (GATHER) {
                    v0 = 0.5f * v0 * (1.0f + erff(v0 * 0.70710678118654752f));
                    v1 = 0.5f * v1 * (1.0f + erff(v1 * 0.70710678118654752f));
                    *(uint32_t*)(g_Hf + (size_t)row * F_DIM + col) =
                        pack_h2(__float2half_rn(v0), __float2half_rn(v1));
                } else {
                    float w = g_roww[row];
                    if (w != 0.0f) {
                        int tok = g_rowtok[row];
                        float* dst = out + (size_t)tok * D_DIM + col;
                        REDADD2(dst, w * v0, w * v1);
                    }
                }
            }
        }
    }
}

// ---------------------------------------------------------------------------
// Launch
// ---------------------------------------------------------------------------
extern "C" void kernel_launch(void* const* d_in, const int* in_sizes, int n_in,
                              void* d_out, int out_size) {
    const float* x  = (const float*)d_in[0];
    const float* rw = (const float*)d_in[1];
    const float* rb = (const float*)d_in[2];
    const float* w1 = (const float*)d_in[3];
    const float* b1 = (const float*)d_in[4];
    const float* w2 = (const float*)d_in[5];
    const float* b2 = (const float*)d_in[6];
    float* out = (float*)d_out;

    static bool attr_done = false;
    if (!attr_done) {
        cudaFuncSetAttribute(moe_gemm<true, D_DIM, F_DIM>,
                             cudaFuncAttributeMaxDynamicSharedMemorySize, SM_TOTAL);
        cudaFuncSetAttribute(moe_gemm<false, F_DIM, D_DIM>,
                             cudaFuncAttributeMaxDynamicSharedMemorySize, SM_TOTAL);
        attr_done = true;
    }

    __half* w2f;
    cudaGetSymbolAddress((void**)&w2f, g_w2f);

    reset_kernel<<<1, 32>>>();
    prep_kernel<<<dim3(512, 4), 256>>>(x, rw, rb, (const float4*)w1, out);
    setup_kernel<<<1, 256>>>();
    scatter_kernel<<<(T_TOK * K_TOP + 255) / 256, 256>>>();

    // GEMM1 grid: y==0 -> w2 conversion (overlapped); y in [1,ROWTILES] -> tiles
    int w2n4 = E_NUM * F_DIM * D_DIM / 4;
    moe_gemm<true, D_DIM, F_DIM>
        <<<dim3(F_DIM / BN, ROWTILES + 1), 256, SM_TOTAL>>>(
            b1, nullptr, (const float4*)w2, w2f, w2n4);
    moe_gemm<false, F_DIM, D_DIM>
        <<<dim3(D_DIM / BN, ROWTILES), 256, SM_TOTAL>>>(
            b2, out, nullptr, nullptr, 0);
}